// round 1
// baseline (speedup 1.0000x reference)
#include <cuda_runtime.h>
#include <cuda_bf16.h>
#include <math.h>

// Problem dims (fixed by setup_inputs)
#define BB   4
#define NPTS 2048
#define LL   4096      // 2*NPTS
#define EE   128
#define DI   256
#define DS   16
#define DR   8
#define NXD  40        // DR + 2*DS
#define DC   4
#define NC   40
#define BL   (BB*LL)   // 16384 rows

// -------- scratch (static device globals; no runtime allocation) --------
__device__ float g_h   [(size_t)BL*EE];     // residual stream      8 MB
__device__ float g_xn  [(size_t)BL*EE];     // LN output            8 MB
__device__ float g_uz  [(size_t)BL*2*DI];   // inproj out          32 MB
__device__ float g_uc  [(size_t)BL*DI];     // conv+silu out       16 MB
__device__ float g_xdbl[(size_t)BL*NXD];    // xproj out          2.6 MB
__device__ float g_delta[(size_t)BL*DI];    // softplus(dt)        16 MB
__device__ float g_y   [(size_t)BL*DI];     // scan out (gated)    16 MB
__device__ float g_acc [BB*EE];             // final LN mean accum

__device__ __forceinline__ float siluf(float x) { return x / (1.f + expf(-x)); }
__device__ __forceinline__ float softplusf(float x) {
    return fmaxf(x, 0.f) + log1pf(expf(-fabsf(x)));
}

// -------- 0) gather + positional embed --------
__global__ void k_embed(const float* __restrict__ x,
                        const int* __restrict__ oh, const int* __restrict__ ot,
                        const float* __restrict__ pew, const float* __restrict__ peb,
                        const float* __restrict__ gamma, const float* __restrict__ beta)
{
    int bl = blockIdx.x;              // 0..BL-1
    int b = bl >> 12, l = bl & (LL-1);
    int e = threadIdx.x;
    int gi, idx;
    if (l < NPTS) { gi = 0; idx = oh[b*NPTS + l]; }
    else          { gi = 1; idx = ot[b*NPTS + (l - NPTS)]; }
    const float* p = x + ((size_t)b*NPTS + idx)*3;
    float px = p[0], py = p[1], pz = p[2];
    float v = pew[e*3+0]*px + pew[e*3+1]*py + pew[e*3+2]*pz + peb[e];
    v = v * gamma[gi*EE + e] + beta[gi*EE + e];
    g_h[(size_t)bl*EE + e] = v;
}

// -------- 1) LayerNorm over E=128 (one row per block, 128 threads) --------
__global__ void k_ln(const float* __restrict__ g, const float* __restrict__ bbv)
{
    int row = blockIdx.x;
    int e   = threadIdx.x;
    float v = g_h[(size_t)row*EE + e];
    float a = v, a2 = v*v;
    #pragma unroll
    for (int o = 16; o > 0; o >>= 1) {
        a  += __shfl_xor_sync(~0u, a,  o);
        a2 += __shfl_xor_sync(~0u, a2, o);
    }
    __shared__ float s1[4], s2[4];
    int w = e >> 5;
    if ((e & 31) == 0) { s1[w] = a; s2[w] = a2; }
    __syncthreads();
    float sum  = s1[0] + s1[1] + s1[2] + s1[3];
    float sumq = s2[0] + s2[1] + s2[2] + s2[3];
    float m   = sum  * (1.f/EE);
    float var = sumq * (1.f/EE) - m*m;
    float xn = (v - m) * rsqrtf(var + 1e-5f) * g[e] + bbv[e];
    g_xn[(size_t)row*EE + e] = xn;
}

// -------- generic SGEMM: C[M,N] (+)= A[M,K] * W[N,K]^T --------
// 64x64 tile, BK=16, 256 threads, 4x4 per-thread micro-tile
__global__ void k_sgemm_nt(const float* __restrict__ A, const float* __restrict__ W,
                           float* __restrict__ C, int M, int N, int K, int accum)
{
    __shared__ float As[16][64];
    __shared__ float Ws[16][64];
    int bm = blockIdx.y * 64;
    int bn = blockIdx.x * 64;
    int tid = threadIdx.x;
    int tx = tid & 15, ty = tid >> 4;
    int la  = tid * 4;
    int lam = la >> 4, lak = la & 15;   // (row-in-tile, k-in-tile), float4 granularity

    float acc[4][4];
    #pragma unroll
    for (int i = 0; i < 4; i++)
        #pragma unroll
        for (int j = 0; j < 4; j++) acc[i][j] = 0.f;

    for (int k0 = 0; k0 < K; k0 += 16) {
        float4 va = make_float4(0,0,0,0), vw = make_float4(0,0,0,0);
        int gm = bm + lam;
        if (gm < M) va = *(const float4*)(A + (size_t)gm*K + k0 + lak);
        int gn = bn + lam;
        if (gn < N) vw = *(const float4*)(W + (size_t)gn*K + k0 + lak);
        __syncthreads();
        As[lak+0][lam] = va.x; As[lak+1][lam] = va.y;
        As[lak+2][lam] = va.z; As[lak+3][lam] = va.w;
        Ws[lak+0][lam] = vw.x; Ws[lak+1][lam] = vw.y;
        Ws[lak+2][lam] = vw.z; Ws[lak+3][lam] = vw.w;
        __syncthreads();
        #pragma unroll
        for (int k = 0; k < 16; k++) {
            float ar[4], wr[4];
            *(float4*)ar = *(const float4*)&As[k][ty*4];
            *(float4*)wr = *(const float4*)&Ws[k][tx*4];
            #pragma unroll
            for (int i = 0; i < 4; i++)
                #pragma unroll
                for (int j = 0; j < 4; j++)
                    acc[i][j] += ar[i] * wr[j];
        }
    }
    #pragma unroll
    for (int i = 0; i < 4; i++) {
        int row = bm + ty*4 + i;
        if (row >= M) continue;
        #pragma unroll
        for (int j = 0; j < 4; j++) {
            int col = bn + tx*4 + j;
            if (col >= N) continue;
            size_t o = (size_t)row*N + col;
            C[o] = accum ? (C[o] + acc[i][j]) : acc[i][j];
        }
    }
}

// -------- 2) depthwise causal conv (width 4) + SiLU --------
__global__ void k_conv(const float* __restrict__ cw, const float* __restrict__ cb)
{
    int row = blockIdx.x;            // b*LL + l
    int d   = threadIdx.x;           // 0..255
    int b = row >> 12, l = row & (LL-1);
    const float* u = g_uz;           // u = first DI cols of uz, row stride 2*DI
    size_t base = ((size_t)b*LL)*(2*DI) + d;
    float w0 = cw[d*DC+0], w1 = cw[d*DC+1], w2 = cw[d*DC+2], w3 = cw[d*DC+3];
    float acc = cb[d];
    if (l >= 3) acc += u[base + (size_t)(l-3)*(2*DI)] * w0;
    if (l >= 2) acc += u[base + (size_t)(l-2)*(2*DI)] * w1;
    if (l >= 1) acc += u[base + (size_t)(l-1)*(2*DI)] * w2;
    acc += u[base + (size_t)l*(2*DI)] * w3;
    g_uc[(size_t)row*DI + d] = siluf(acc);
}

// -------- 3) delta = softplus(dt @ dtw^T + dtb) --------
__global__ void k_delta(const float* __restrict__ dtw, const float* __restrict__ dtb)
{
    int row = blockIdx.x;
    int d   = threadIdx.x;           // 0..255
    __shared__ float dts[DR];
    if (d < DR) dts[d] = g_xdbl[(size_t)row*NXD + d];
    __syncthreads();
    float acc = dtb[d];
    #pragma unroll
    for (int r = 0; r < DR; r++) acc += dts[r] * dtw[d*DR + r];
    g_delta[(size_t)row*DI + d] = softplusf(acc);
}

// -------- 4) selective scan: one warp = 2 channels, 16 states/lane-group --------
__global__ void k_scan(const float* __restrict__ Alog, const float* __restrict__ Dpv)
{
    int lane = threadIdx.x;            // 0..31
    int grp  = lane >> 4;              // channel within warp
    int s    = lane & 15;              // state index
    int chan = blockIdx.x * 2 + grp;   // 0..1023
    int b = chan >> 8, d = chan & 255;

    float A  = -expf(Alog[d*DS + s]);
    float Dd = Dpv[d];
    float h = 0.f;

    size_t base_du = (size_t)b*LL*DI + d;            // delta / uc / y
    size_t base_x  = (size_t)b*LL*NXD;               // xdbl
    size_t base_z  = (size_t)b*LL*(2*DI) + DI + d;   // z in uz

    for (int t = 0; t < LL; t++) {
        float delta = g_delta[base_du + (size_t)t*DI];
        float u     = g_uc   [base_du + (size_t)t*DI];
        float Bt    = g_xdbl [base_x + (size_t)t*NXD + DR + s];
        float Ct    = g_xdbl [base_x + (size_t)t*NXD + DR + DS + s];
        float a = expf(delta * A);
        h = a*h + (delta*u)*Bt;
        float p = h * Ct;
        p += __shfl_xor_sync(~0u, p, 8, 16);
        p += __shfl_xor_sync(~0u, p, 4, 16);
        p += __shfl_xor_sync(~0u, p, 2, 16);
        p += __shfl_xor_sync(~0u, p, 1, 16);
        if (s == 0) {
            float z = g_uz[base_z + (size_t)t*(2*DI)];
            float y = p + Dd*u;
            y *= siluf(z);
            g_y[base_du + (size_t)t*DI] = y;
        }
    }
}

// -------- 5) final: zero accum, LN+mean accumulate, fc --------
__global__ void k_zero()
{
    int t = threadIdx.x;
    if (t < BB*EE) g_acc[t] = 0.f;
}

__global__ void k_finacc(const float* __restrict__ gg, const float* __restrict__ gb)
{
    int b     = blockIdx.x >> 4;
    int chunk = blockIdx.x & 15;
    int w    = threadIdx.x >> 5;       // warp 0..7
    int lane = threadIdx.x & 31;
    float g0 = gg[lane], g1 = gg[lane+32], g2 = gg[lane+64], g3 = gg[lane+96];
    float b0 = gb[lane], b1 = gb[lane+32], b2 = gb[lane+64], b3 = gb[lane+96];
    float a0=0.f, a1=0.f, a2=0.f, a3=0.f;
    for (int j = 0; j < 32; j++) {
        int l = chunk*256 + j*8 + w;
        const float* row = g_h + ((size_t)b*LL + l)*EE;
        float x0 = row[lane], x1 = row[lane+32], x2 = row[lane+64], x3 = row[lane+96];
        float sv = x0+x1+x2+x3;
        float sq = x0*x0 + x1*x1 + x2*x2 + x3*x3;
        #pragma unroll
        for (int o = 16; o > 0; o >>= 1) {
            sv += __shfl_xor_sync(~0u, sv, o);
            sq += __shfl_xor_sync(~0u, sq, o);
        }
        float m   = sv * (1.f/EE);
        float var = sq * (1.f/EE) - m*m;
        float inv = rsqrtf(var + 1e-5f);
        a0 += (x0-m)*inv*g0 + b0;
        a1 += (x1-m)*inv*g1 + b1;
        a2 += (x2-m)*inv*g2 + b2;
        a3 += (x3-m)*inv*g3 + b3;
    }
    atomicAdd(&g_acc[b*EE + lane     ], a0);
    atomicAdd(&g_acc[b*EE + lane + 32], a1);
    atomicAdd(&g_acc[b*EE + lane + 64], a2);
    atomicAdd(&g_acc[b*EE + lane + 96], a3);
}

__global__ void k_fc(const float* __restrict__ fcw, const float* __restrict__ fcb,
                     float* __restrict__ out)
{
    int t = threadIdx.x;
    if (t >= BB*NC) return;
    int b = t / NC, c = t % NC;
    float acc = 0.f;
    #pragma unroll 4
    for (int e = 0; e < EE; e++) acc += g_acc[b*EE + e] * fcw[c*EE + e];
    out[t] = acc * (1.f/LL) + fcb[c];
}

// ----------------------------------------------------------------------------
extern "C" void kernel_launch(void* const* d_in, const int* in_sizes, int n_in,
                              void* d_out, int out_size)
{
    const float* x        = (const float*)d_in[0];
    const int*   order_h  = (const int*)  d_in[1];
    const int*   order_t  = (const int*)  d_in[2];
    const float* pe_w     = (const float*)d_in[3];
    const float* pe_b     = (const float*)d_in[4];
    const float* gamma    = (const float*)d_in[5];
    const float* beta     = (const float*)d_in[6];
    const float* ln_g     = (const float*)d_in[7];
    const float* ln_b     = (const float*)d_in[8];
    const float* inproj_w = (const float*)d_in[9];
    const float* conv_w   = (const float*)d_in[10];
    const float* conv_b   = (const float*)d_in[11];
    const float* xproj_w  = (const float*)d_in[12];
    const float* dtproj_w = (const float*)d_in[13];
    const float* dtproj_b = (const float*)d_in[14];
    const float* A_log    = (const float*)d_in[15];
    const float* Dp       = (const float*)d_in[16];
    const float* outproj_w= (const float*)d_in[17];
    const float* hn_g     = (const float*)d_in[18];
    const float* hn_b     = (const float*)d_in[19];
    const float* fc_w     = (const float*)d_in[20];
    const float* fc_b     = (const float*)d_in[21];
    float* out = (float*)d_out;

    // resolve scratch addresses (no allocation; symbols already resident)
    float *p_xn, *p_uz, *p_uc, *p_xdbl, *p_y, *p_h;
    cudaGetSymbolAddress((void**)&p_xn,   g_xn);
    cudaGetSymbolAddress((void**)&p_uz,   g_uz);
    cudaGetSymbolAddress((void**)&p_uc,   g_uc);
    cudaGetSymbolAddress((void**)&p_xdbl, g_xdbl);
    cudaGetSymbolAddress((void**)&p_y,    g_y);
    cudaGetSymbolAddress((void**)&p_h,    g_h);

    k_embed<<<BL, EE>>>(x, order_h, order_t, pe_w, pe_b, gamma, beta);

    for (int i = 0; i < 2; i++) {
        k_ln<<<BL, EE>>>(ln_g + i*EE, ln_b + i*EE);
        // uz = xn @ inproj^T   (M=16384, N=512, K=128)
        k_sgemm_nt<<<dim3((2*DI)/64, BL/64), 256>>>(
            p_xn, inproj_w + (size_t)i*2*DI*EE, p_uz, BL, 2*DI, EE, 0);
        k_conv<<<BL, DI>>>(conv_w + (size_t)i*DI*DC, conv_b + (size_t)i*DI);
        // xdbl = uc @ xproj^T  (M=16384, N=40, K=256)
        k_sgemm_nt<<<dim3(1, BL/64), 256>>>(
            p_uc, xproj_w + (size_t)i*NXD*DI, p_xdbl, BL, NXD, DI, 0);
        k_delta<<<BL, DI>>>(dtproj_w + (size_t)i*DI*DR, dtproj_b + (size_t)i*DI);
        k_scan<<<(BB*DI)/2, 32>>>(A_log + (size_t)i*DI*DS, Dp + (size_t)i*DI);
        // h += y @ outproj^T   (M=16384, N=128, K=256), accumulate
        k_sgemm_nt<<<dim3(EE/64, BL/64), 256>>>(
            p_y, outproj_w + (size_t)i*EE*DI, p_h, BL, EE, DI, 1);
    }

    k_zero<<<1, 512>>>();
    k_finacc<<<BB*16, 256>>>(hn_g, hn_b);
    k_fc<<<1, 192>>>(fc_w, fc_b, out);
}

// round 2
// speedup vs baseline: 7.5001x; 7.5001x over previous
#include <cuda_runtime.h>
#include <cuda_bf16.h>
#include <math.h>

// Problem dims (fixed by setup_inputs)
#define BB   4
#define NPTS 2048
#define LL   4096      // 2*NPTS
#define EE   128
#define DI   256
#define DS   16
#define DR   8
#define NXD  40        // DR + 2*DS
#define DC   4
#define NC   40
#define BL   (BB*LL)   // 16384 rows
#define NCH  32        // scan chunks
#define CL   128       // chunk length (NCH*CL == LL)
#define NCHAN (BB*DI)  // 1024 scan channels

// -------- scratch (static device globals; no runtime allocation) --------
__device__ float g_h   [(size_t)BL*EE];     // residual stream      8 MB
__device__ float g_xn  [(size_t)BL*EE];     // LN output            8 MB
__device__ float g_uz  [(size_t)BL*2*DI];   // inproj out          32 MB
__device__ float g_uc  [(size_t)BL*DI];     // conv+silu out       16 MB
__device__ float g_xdbl[(size_t)BL*NXD];    // xproj out          2.6 MB
__device__ float g_delta[(size_t)BL*DI];    // softplus(dt)        16 MB
__device__ float g_y   [(size_t)BL*DI];     // scan out (gated)    16 MB
__device__ float g_acc [BB*EE];             // final LN mean accum
__device__ float g_hend[(size_t)NCHAN*NCH*DS]; // chunk end states  2 MB
__device__ float g_h0  [(size_t)NCHAN*NCH*DS]; // chunk init states 2 MB
__device__ float g_sd  [(size_t)NCHAN*NCH];    // chunk sum(delta)

__device__ __forceinline__ float siluf(float x) { return x / (1.f + expf(-x)); }
__device__ __forceinline__ float softplusf(float x) {
    return fmaxf(x, 0.f) + log1pf(expf(-fabsf(x)));
}

// -------- 0) gather + positional embed --------
__global__ void k_embed(const float* __restrict__ x,
                        const int* __restrict__ oh, const int* __restrict__ ot,
                        const float* __restrict__ pew, const float* __restrict__ peb,
                        const float* __restrict__ gamma, const float* __restrict__ beta)
{
    int bl = blockIdx.x;              // 0..BL-1
    int b = bl >> 12, l = bl & (LL-1);
    int e = threadIdx.x;
    int gi, idx;
    if (l < NPTS) { gi = 0; idx = oh[b*NPTS + l]; }
    else          { gi = 1; idx = ot[b*NPTS + (l - NPTS)]; }
    const float* p = x + ((size_t)b*NPTS + idx)*3;
    float px = p[0], py = p[1], pz = p[2];
    float v = pew[e*3+0]*px + pew[e*3+1]*py + pew[e*3+2]*pz + peb[e];
    v = v * gamma[gi*EE + e] + beta[gi*EE + e];
    g_h[(size_t)bl*EE + e] = v;
}

// -------- 1) LayerNorm over E=128 (one row per block, 128 threads) --------
__global__ void k_ln(const float* __restrict__ g, const float* __restrict__ bbv)
{
    int row = blockIdx.x;
    int e   = threadIdx.x;
    float v = g_h[(size_t)row*EE + e];
    float a = v, a2 = v*v;
    #pragma unroll
    for (int o = 16; o > 0; o >>= 1) {
        a  += __shfl_xor_sync(~0u, a,  o);
        a2 += __shfl_xor_sync(~0u, a2, o);
    }
    __shared__ float s1[4], s2[4];
    int w = e >> 5;
    if ((e & 31) == 0) { s1[w] = a; s2[w] = a2; }
    __syncthreads();
    float sum  = s1[0] + s1[1] + s1[2] + s1[3];
    float sumq = s2[0] + s2[1] + s2[2] + s2[3];
    float m   = sum  * (1.f/EE);
    float var = sumq * (1.f/EE) - m*m;
    float xn = (v - m) * rsqrtf(var + 1e-5f) * g[e] + bbv[e];
    g_xn[(size_t)row*EE + e] = xn;
}

// -------- generic SGEMM: C[M,N] (+)= A[M,K] * W[N,K]^T --------
__global__ void k_sgemm_nt(const float* __restrict__ A, const float* __restrict__ W,
                           float* __restrict__ C, int M, int N, int K, int accum)
{
    __shared__ float As[16][64];
    __shared__ float Ws[16][64];
    int bm = blockIdx.y * 64;
    int bn = blockIdx.x * 64;
    int tid = threadIdx.x;
    int tx = tid & 15, ty = tid >> 4;
    int la  = tid * 4;
    int lam = la >> 4, lak = la & 15;

    float acc[4][4];
    #pragma unroll
    for (int i = 0; i < 4; i++)
        #pragma unroll
        for (int j = 0; j < 4; j++) acc[i][j] = 0.f;

    for (int k0 = 0; k0 < K; k0 += 16) {
        float4 va = make_float4(0,0,0,0), vw = make_float4(0,0,0,0);
        int gm = bm + lam;
        if (gm < M) va = *(const float4*)(A + (size_t)gm*K + k0 + lak);
        int gn = bn + lam;
        if (gn < N) vw = *(const float4*)(W + (size_t)gn*K + k0 + lak);
        __syncthreads();
        As[lak+0][lam] = va.x; As[lak+1][lam] = va.y;
        As[lak+2][lam] = va.z; As[lak+3][lam] = va.w;
        Ws[lak+0][lam] = vw.x; Ws[lak+1][lam] = vw.y;
        Ws[lak+2][lam] = vw.z; Ws[lak+3][lam] = vw.w;
        __syncthreads();
        #pragma unroll
        for (int k = 0; k < 16; k++) {
            float ar[4], wr[4];
            *(float4*)ar = *(const float4*)&As[k][ty*4];
            *(float4*)wr = *(const float4*)&Ws[k][tx*4];
            #pragma unroll
            for (int i = 0; i < 4; i++)
                #pragma unroll
                for (int j = 0; j < 4; j++)
                    acc[i][j] += ar[i] * wr[j];
        }
    }
    #pragma unroll
    for (int i = 0; i < 4; i++) {
        int row = bm + ty*4 + i;
        if (row >= M) continue;
        #pragma unroll
        for (int j = 0; j < 4; j++) {
            int col = bn + tx*4 + j;
            if (col >= N) continue;
            size_t o = (size_t)row*N + col;
            C[o] = accum ? (C[o] + acc[i][j]) : acc[i][j];
        }
    }
}

// -------- 2) depthwise causal conv (width 4) + SiLU --------
__global__ void k_conv(const float* __restrict__ cw, const float* __restrict__ cb)
{
    int row = blockIdx.x;            // b*LL + l
    int d   = threadIdx.x;           // 0..255
    int b = row >> 12, l = row & (LL-1);
    const float* u = g_uz;
    size_t base = ((size_t)b*LL)*(2*DI) + d;
    float w0 = cw[d*DC+0], w1 = cw[d*DC+1], w2 = cw[d*DC+2], w3 = cw[d*DC+3];
    float acc = cb[d];
    if (l >= 3) acc += u[base + (size_t)(l-3)*(2*DI)] * w0;
    if (l >= 2) acc += u[base + (size_t)(l-2)*(2*DI)] * w1;
    if (l >= 1) acc += u[base + (size_t)(l-1)*(2*DI)] * w2;
    acc += u[base + (size_t)l*(2*DI)] * w3;
    g_uc[(size_t)row*DI + d] = siluf(acc);
}

// -------- 3) delta = softplus(dt @ dtw^T + dtb) --------
__global__ void k_delta(const float* __restrict__ dtw, const float* __restrict__ dtb)
{
    int row = blockIdx.x;
    int d   = threadIdx.x;           // 0..255
    __shared__ float dts[DR];
    if (d < DR) dts[d] = g_xdbl[(size_t)row*NXD + d];
    __syncthreads();
    float acc = dtb[d];
    #pragma unroll
    for (int r = 0; r < DR; r++) acc += dts[r] * dtw[d*DR + r];
    g_delta[(size_t)row*DI + d] = softplusf(acc);
}

// -------- 4a) chunk scan pass A: per-chunk end state (h starts at 0) --------
// warp w -> (pair = w % 512, chunk = w / 512); lane: grp=lane>>4 (channel in
// pair), s=lane&15 (state). 16384 warps total.
__global__ void k_scanA(const float* __restrict__ Alog)
{
    int w    = blockIdx.x * 8 + (threadIdx.x >> 5);
    int lane = threadIdx.x & 31;
    int grp  = lane >> 4;
    int s    = lane & 15;
    int pair = w & 511;
    int c    = w >> 9;
    int chan = pair*2 + grp;
    int b = chan >> 8, d = chan & 255;

    float A = -expf(Alog[d*DS + s]);
    float h = 0.f, sd = 0.f;

    size_t base_du = (size_t)b*LL*DI + d;
    size_t base_x  = (size_t)b*LL*NXD;
    int t0 = c*CL;

    #pragma unroll 4
    for (int tt = 0; tt < CL; tt++) {
        int t = t0 + tt;
        float delta = g_delta[base_du + (size_t)t*DI];
        float u     = g_uc   [base_du + (size_t)t*DI];
        float Bt    = g_xdbl [base_x + (size_t)t*NXD + DR + s];
        float a = expf(delta * A);
        h = a*h + (delta*u)*Bt;
        sd += delta;
    }
    g_hend[((size_t)chan*NCH + c)*DS + s] = h;
    if (s == 0) g_sd[(size_t)chan*NCH + c] = sd;
}

// -------- 4b) stitch chunk initial states (sequential over 32 chunks) -------
// 512 warps, each handles a channel pair.
__global__ void k_scanB(const float* __restrict__ Alog)
{
    int w    = blockIdx.x * 8 + (threadIdx.x >> 5);
    int lane = threadIdx.x & 31;
    int grp  = lane >> 4;
    int s    = lane & 15;
    int chan = w*2 + grp;
    int d = chan & 255;

    float A = -expf(Alog[d*DS + s]);
    float h0 = 0.f;
    size_t base = (size_t)chan*NCH;
    for (int c = 0; c < NCH; c++) {
        g_h0[(base + c)*DS + s] = h0;
        float P = expf(A * g_sd[base + c]);
        h0 = P*h0 + g_hend[(base + c)*DS + s];
    }
}

// -------- 4c) chunk scan pass C: full recurrence from h0, emit gated y ------
__global__ void k_scanC(const float* __restrict__ Alog, const float* __restrict__ Dpv)
{
    int w    = blockIdx.x * 8 + (threadIdx.x >> 5);
    int lane = threadIdx.x & 31;
    int grp  = lane >> 4;
    int s    = lane & 15;
    int pair = w & 511;
    int c    = w >> 9;
    int chan = pair*2 + grp;
    int b = chan >> 8, d = chan & 255;

    float A  = -expf(Alog[d*DS + s]);
    float Dd = Dpv[d];
    float h  = g_h0[((size_t)chan*NCH + c)*DS + s];

    size_t base_du = (size_t)b*LL*DI + d;
    size_t base_x  = (size_t)b*LL*NXD;
    size_t base_z  = (size_t)b*LL*(2*DI) + DI + d;
    int t0 = c*CL;

    #pragma unroll 2
    for (int tt = 0; tt < CL; tt++) {
        int t = t0 + tt;
        float delta = g_delta[base_du + (size_t)t*DI];
        float u     = g_uc   [base_du + (size_t)t*DI];
        float Bt    = g_xdbl [base_x + (size_t)t*NXD + DR + s];
        float Ct    = g_xdbl [base_x + (size_t)t*NXD + DR + DS + s];
        float a = expf(delta * A);
        h = a*h + (delta*u)*Bt;
        float p = h * Ct;
        p += __shfl_xor_sync(~0u, p, 8, 16);
        p += __shfl_xor_sync(~0u, p, 4, 16);
        p += __shfl_xor_sync(~0u, p, 2, 16);
        p += __shfl_xor_sync(~0u, p, 1, 16);
        if (s == 0) {
            float z = g_uz[base_z + (size_t)t*(2*DI)];
            float y = p + Dd*u;
            y *= siluf(z);
            g_y[base_du + (size_t)t*DI] = y;
        }
    }
}

// -------- 5) final: zero accum, LN+mean accumulate, fc --------
__global__ void k_zero()
{
    int t = threadIdx.x;
    if (t < BB*EE) g_acc[t] = 0.f;
}

__global__ void k_finacc(const float* __restrict__ gg, const float* __restrict__ gb)
{
    int b     = blockIdx.x >> 4;
    int chunk = blockIdx.x & 15;
    int w    = threadIdx.x >> 5;
    int lane = threadIdx.x & 31;
    float g0 = gg[lane], g1 = gg[lane+32], g2 = gg[lane+64], g3 = gg[lane+96];
    float b0 = gb[lane], b1 = gb[lane+32], b2 = gb[lane+64], b3 = gb[lane+96];
    float a0=0.f, a1=0.f, a2=0.f, a3=0.f;
    for (int j = 0; j < 32; j++) {
        int l = chunk*256 + j*8 + w;
        const float* row = g_h + ((size_t)b*LL + l)*EE;
        float x0 = row[lane], x1 = row[lane+32], x2 = row[lane+64], x3 = row[lane+96];
        float sv = x0+x1+x2+x3;
        float sq = x0*x0 + x1*x1 + x2*x2 + x3*x3;
        #pragma unroll
        for (int o = 16; o > 0; o >>= 1) {
            sv += __shfl_xor_sync(~0u, sv, o);
            sq += __shfl_xor_sync(~0u, sq, o);
        }
        float m   = sv * (1.f/EE);
        float var = sq * (1.f/EE) - m*m;
        float inv = rsqrtf(var + 1e-5f);
        a0 += (x0-m)*inv*g0 + b0;
        a1 += (x1-m)*inv*g1 + b1;
        a2 += (x2-m)*inv*g2 + b2;
        a3 += (x3-m)*inv*g3 + b3;
    }
    atomicAdd(&g_acc[b*EE + lane     ], a0);
    atomicAdd(&g_acc[b*EE + lane + 32], a1);
    atomicAdd(&g_acc[b*EE + lane + 64], a2);
    atomicAdd(&g_acc[b*EE + lane + 96], a3);
}

__global__ void k_fc(const float* __restrict__ fcw, const float* __restrict__ fcb,
                     float* __restrict__ out)
{
    int t = threadIdx.x;
    if (t >= BB*NC) return;
    int b = t / NC, c = t % NC;
    float acc = 0.f;
    #pragma unroll 4
    for (int e = 0; e < EE; e++) acc += g_acc[b*EE + e] * fcw[c*EE + e];
    out[t] = acc * (1.f/LL) + fcb[c];
}

// ----------------------------------------------------------------------------
extern "C" void kernel_launch(void* const* d_in, const int* in_sizes, int n_in,
                              void* d_out, int out_size)
{
    const float* x        = (const float*)d_in[0];
    const int*   order_h  = (const int*)  d_in[1];
    const int*   order_t  = (const int*)  d_in[2];
    const float* pe_w     = (const float*)d_in[3];
    const float* pe_b     = (const float*)d_in[4];
    const float* gamma    = (const float*)d_in[5];
    const float* beta     = (const float*)d_in[6];
    const float* ln_g     = (const float*)d_in[7];
    const float* ln_b     = (const float*)d_in[8];
    const float* inproj_w = (const float*)d_in[9];
    const float* conv_w   = (const float*)d_in[10];
    const float* conv_b   = (const float*)d_in[11];
    const float* xproj_w  = (const float*)d_in[12];
    const float* dtproj_w = (const float*)d_in[13];
    const float* dtproj_b = (const float*)d_in[14];
    const float* A_log    = (const float*)d_in[15];
    const float* Dp       = (const float*)d_in[16];
    const float* outproj_w= (const float*)d_in[17];
    const float* hn_g     = (const float*)d_in[18];
    const float* hn_b     = (const float*)d_in[19];
    const float* fc_w     = (const float*)d_in[20];
    const float* fc_b     = (const float*)d_in[21];
    float* out = (float*)d_out;

    float *p_xn, *p_uz, *p_uc, *p_xdbl, *p_y, *p_h;
    cudaGetSymbolAddress((void**)&p_xn,   g_xn);
    cudaGetSymbolAddress((void**)&p_uz,   g_uz);
    cudaGetSymbolAddress((void**)&p_uc,   g_uc);
    cudaGetSymbolAddress((void**)&p_xdbl, g_xdbl);
    cudaGetSymbolAddress((void**)&p_y,    g_y);
    cudaGetSymbolAddress((void**)&p_h,    g_h);

    k_embed<<<BL, EE>>>(x, order_h, order_t, pe_w, pe_b, gamma, beta);

    for (int i = 0; i < 2; i++) {
        k_ln<<<BL, EE>>>(ln_g + i*EE, ln_b + i*EE);
        // uz = xn @ inproj^T   (M=16384, N=512, K=128)
        k_sgemm_nt<<<dim3((2*DI)/64, BL/64), 256>>>(
            p_xn, inproj_w + (size_t)i*2*DI*EE, p_uz, BL, 2*DI, EE, 0);
        k_conv<<<BL, DI>>>(conv_w + (size_t)i*DI*DC, conv_b + (size_t)i*DI);
        // xdbl = uc @ xproj^T  (M=16384, N=40, K=256)
        k_sgemm_nt<<<dim3(1, BL/64), 256>>>(
            p_uc, xproj_w + (size_t)i*NXD*DI, p_xdbl, BL, NXD, DI, 0);
        k_delta<<<BL, DI>>>(dtproj_w + (size_t)i*DI*DR, dtproj_b + (size_t)i*DI);
        // chunked selective scan
        k_scanA<<<2048, 256>>>(A_log + (size_t)i*DI*DS);
        k_scanB<<<64, 256>>>(A_log + (size_t)i*DI*DS);
        k_scanC<<<2048, 256>>>(A_log + (size_t)i*DI*DS, Dp + (size_t)i*DI);
        // h += y @ outproj^T   (M=16384, N=128, K=256), accumulate
        k_sgemm_nt<<<dim3(EE/64, BL/64), 256>>>(
            p_y, outproj_w + (size_t)i*EE*DI, p_h, BL, EE, DI, 1);
    }

    k_zero<<<1, 512>>>();
    k_finacc<<<BB*16, 256>>>(hn_g, hn_b);
    k_fc<<<1, 192>>>(fc_w, fc_b, out);
}